// round 1
// baseline (speedup 1.0000x reference)
#include <cuda_runtime.h>

#define BATCH 4096
#define NN 64
#define HH 16
#define FALLBACK_SIZE 12

__device__ double g_accum;

__global__ void zero_accum_kernel() { g_accum = 0.0; }

__global__ void finalize_kernel(float* out) {
    out[0] = (float)(g_accum * (1.0 / (double)BATCH));
}

__global__ __launch_bounds__(256) void energy_kernel(
    const float* __restrict__ grid,   // [B,1,64,64]
    const float* __restrict__ hints,  // [B,2,64,16]
    const float* __restrict__ wg,     // [1,64,64]
    const float* __restrict__ wh)     // [2,64,16]
{
    __shared__ float s_row_target[NN];
    __shared__ float s_col_target[NN];
    __shared__ float s_colpart[8 * NN];   // per-warp column partial sums
    __shared__ float s_warp[8];
    __shared__ int   s_size;

    const int b = blockIdx.x;
    const int t = threadIdx.x;
    const int lane = t & 31;
    const int wid  = t >> 5;

    const float* gb = grid  + (size_t)b * (NN * NN);
    const float* hb = hints + (size_t)b * (2 * NN * HH);

    float neural = 0.f;

    // ---- Phase 1: hints -> targets + neural(hints . w_h) ----
    if (t < 128) {
        const int k = t >> 6;      // 0 = row hints, 1 = col hints
        const int i = t & 63;
        const float4* hp = (const float4*)(hb + k * (NN * HH) + i * HH);
        const float4* wp = (const float4*)(wh + k * (NN * HH) + i * HH);
        float tsum = 0.f;
        #pragma unroll
        for (int q = 0; q < 4; q++) {
            float4 h4 = hp[q];
            float4 w4 = wp[q];
            tsum  += h4.x + h4.y + h4.z + h4.w;
            neural += h4.x * w4.x + h4.y * w4.y + h4.z * w4.z + h4.w * w4.w;
        }
        if (k == 0) s_row_target[i] = tsum;
        else        s_col_target[i] = tsum;
    }
    __syncthreads();

    // ---- Phase 2: puzzle size from last nonzero target ----
    if (t == 0) {
        int last_r = -1, last_c = -1;
        for (int i = NN - 1; i >= 0; i--) if (s_row_target[i] > 0.f) { last_r = i; break; }
        for (int i = NN - 1; i >= 0; i--) if (s_col_target[i] > 0.f) { last_c = i; break; }
        s_size = (last_r >= 0 && last_c >= 0) ? (max(last_r, last_c) + 1) : FALLBACK_SIZE;
    }
    __syncthreads();
    const int size = s_size;
    const float sz = (float)size;

    // ---- Phase 3: grid pass ----
    // thread t -> row i = t/4, column group cg = t%4 (16 contiguous cols)
    const int i  = t >> 2;
    const int cg = t & 3;
    const bool rin = (i < size);

    const float4* gp  = (const float4*)(gb + i * NN + cg * 16);
    const float4* wgp = (const float4*)(wg + i * NN + cg * 16);

    float csg[16];          // masked sigmoid values for column reduction
    float rowacc = 0.f;     // actual_rows partial (this thread's 16 cols)
    float binsum = 0.f;     // masked grid^2 partial

    #pragma unroll
    for (int q = 0; q < 4; q++) {
        float4 g4 = gp[q];
        float4 w4 = wgp[q];
        float gs[4] = {g4.x, g4.y, g4.z, g4.w};
        float ws[4] = {w4.x, w4.y, w4.z, w4.w};
        #pragma unroll
        for (int e = 0; e < 4; e++) {
            const int j = cg * 16 + q * 4 + e;
            const float g = gs[e];
            neural += g * ws[e];
            const float s = 1.f / (1.f + __expf(-3.f * g));
            const bool jin = (j < size);
            if (jin) rowacc += s;
            if (rin && jin) binsum += g * g;
            csg[q * 4 + e] = rin ? s : 0.f;   // column contribution needs m[i]
        }
    }

    // actual_rows[i]: reduce over the 4 column-group lanes (lanes cg, cg^1, cg^2)
    rowacc += __shfl_xor_sync(0xffffffffu, rowacc, 1);
    rowacc += __shfl_xor_sync(0xffffffffu, rowacc, 2);

    float rowerr = 0.f;
    if (cg == 0 && rin) {
        const float d = rowacc - s_row_target[i];
        rowerr = d * d;
    }

    // actual_cols: reduce csg over the 8 rows present in this warp
    // (lane layout: lane = (i%8)*4 + cg  ->  rows differ by xor 4,8,16)
    #pragma unroll
    for (int x = 0; x < 16; x++) {
        csg[x] += __shfl_xor_sync(0xffffffffu, csg[x], 4);
        csg[x] += __shfl_xor_sync(0xffffffffu, csg[x], 8);
        csg[x] += __shfl_xor_sync(0xffffffffu, csg[x], 16);
    }
    // lanes 0..3 (one per cg) hold this warp's partial for cols cg*16..cg*16+15
    if (lane < 4) {
        #pragma unroll
        for (int x = 0; x < 16; x++)
            s_colpart[wid * NN + lane * 16 + x] = csg[x];
    }
    __syncthreads();

    float colerr = 0.f;
    if (t < NN && t < size) {
        float csum = 0.f;
        #pragma unroll
        for (int w = 0; w < 8; w++) csum += s_colpart[w * NN + t];
        const float d = csum - s_col_target[t];
        colerr = d * d;
    }

    // ---- Combine per-thread energy with proper scale factors ----
    float v = neural
            + (10.f / sz) * (rowerr + colerr)
            + (0.1f / (sz * sz)) * binsum;

    // ---- Block reduction ----
    #pragma unroll
    for (int off = 16; off > 0; off >>= 1)
        v += __shfl_xor_sync(0xffffffffu, v, off);
    if (lane == 0) s_warp[wid] = v;
    __syncthreads();
    if (t < 8) {
        v = s_warp[t];
        v += __shfl_xor_sync(0xffu, v, 4);
        v += __shfl_xor_sync(0xffu, v, 2);
        v += __shfl_xor_sync(0xffu, v, 1);
        if (t == 0) atomicAdd(&g_accum, (double)v);
    }
}

extern "C" void kernel_launch(void* const* d_in, const int* in_sizes, int n_in,
                              void* d_out, int out_size) {
    const float* grid  = (const float*)d_in[0];
    const float* hints = (const float*)d_in[1];
    const float* wg    = (const float*)d_in[2];
    const float* wh    = (const float*)d_in[3];
    float* out = (float*)d_out;

    zero_accum_kernel<<<1, 1>>>();
    energy_kernel<<<BATCH, 256>>>(grid, hints, wg, wh);
    finalize_kernel<<<1, 1>>>(out);
}